// round 15
// baseline (speedup 1.0000x reference)
#include <cuda_runtime.h>
#include <cuda_fp16.h>
#include <cstdint>

#define NN 50000
#define NE 800000
#define INC 256
#define HID 128
#define OUTC 1000
#define TDIM 768

// ---------------- scratch ----------------------------------------------------
__device__ __align__(256) float  g_deg[NN];
__device__ __align__(256) __half g_h1[(size_t)NN * HID];
__device__ __align__(256) __half g_o1[(size_t)NN * HID];
__device__ __align__(256) __half g_h2[(size_t)NN * HID];
__device__ __align__(256) __half g_o2[(size_t)NN * HID];
__device__ __align__(256) float  g_tvec[1024];
__device__ __align__(256) __half g_W2h[HID * HID];
__device__ __align__(256) __half g_Wch[HID * OUTC];
__device__ __align__(256) int    g_ecnt[NN];
__device__ __align__(256) int    g_offs[NN];
__device__ __align__(256) int    g_cursor[NN];
__device__ __align__(256) int    g_esrc[NE];
__device__ int g_counter;

// ---------------- prep kernels ------------------------------------------------
__global__ void init_all(float* deg, float* tvec, const float* __restrict__ bc,
                         int* counter) {
    int i = blockIdx.x * blockDim.x + threadIdx.x;
    if (i == 0) *counter = 0;
    if (i < NN) deg[i] = 1.0f;
    if (i < OUTC) tvec[i] = bc[i];
}
__global__ void deg_count(const int* __restrict__ dst, float* deg) {
    int e = blockIdx.x * blockDim.x + threadIdx.x;
    if (e < NE) atomicAdd(&deg[dst[e]], 1.0f);
}
__global__ void rsqrt_alloc(float* deg, int* ecnt, int* offs, int* cursor,
                            int* counter) {
    int i = blockIdx.x * blockDim.x + threadIdx.x;
    if (i >= NN) return;
    float d = deg[i];
    int c = (int)d - 1;
    ecnt[i] = c;
    deg[i] = rsqrtf(d);
    int base = atomicAdd(counter, c);
    offs[i] = base;
    cursor[i] = base;
}
__global__ void fill_edges(const int* __restrict__ src,
                           const int* __restrict__ dst,
                           int* __restrict__ cursor,
                           int* __restrict__ esrc) {
    int e = blockIdx.x * blockDim.x + threadIdx.x;
    if (e >= NE) return;
    int pos = atomicAdd(&cursor[dst[e]], 1);
    esrc[pos] = src[e];
}
__global__ void convert_half(const float* __restrict__ src,
                             __half* __restrict__ dst, int n) {
    int i = blockIdx.x * blockDim.x + threadIdx.x;
    if (i < n) dst[i] = __float2half_rn(src[i]);
}
__global__ void text_proj_part(const float* __restrict__ text,
                               const float* __restrict__ Wc,
                               float* __restrict__ tvec) {
    int o = blockIdx.x * 128 + threadIdx.x;
    int d0 = blockIdx.y * 128;
    if (o >= OUTC) return;
    float s = 0.f;
    #pragma unroll 8
    for (int d = d0; d < d0 + 128; d++)
        s += text[d] * Wc[(size_t)(HID + d) * OUTC + o];
    atomicAdd(&tvec[o], s);
}

// ---------------- CSR gather (h fp16 in/out, fp32 accumulation) --------------
__global__ void gather_edges(const int* __restrict__ offs,
                             const int* __restrict__ ecnt,
                             const int* __restrict__ esrc,
                             const __half* __restrict__ h,
                             const float* __restrict__ dinv,
                             const float* __restrict__ bias,
                             __half* __restrict__ o) {
    int warp = (blockIdx.x * blockDim.x + threadIdx.x) >> 5;
    int lane = threadIdx.x & 31;
    if (warp >= NN) return;
    int g  = lane >> 4;
    int sl = lane & 15;
    int base = offs[warp];
    int cnt  = ecnt[warp];
    float di = dinv[warp];
    float di2 = di * di;

    float acc[8];
    if (g == 0) {
        float4 b0 = reinterpret_cast<const float4*>(bias)[sl * 2];
        float4 b1 = reinterpret_cast<const float4*>(bias)[sl * 2 + 1];
        acc[0] = b0.x; acc[1] = b0.y; acc[2] = b0.z; acc[3] = b0.w;
        acc[4] = b1.x; acc[5] = b1.y; acc[6] = b1.z; acc[7] = b1.w;
        uint4 raw = reinterpret_cast<const uint4*>(h + (size_t)warp * HID)[sl];
        float2 f;
        f = __half22float2(*reinterpret_cast<__half2*>(&raw.x));
        acc[0] += f.x * di2; acc[1] += f.y * di2;
        f = __half22float2(*reinterpret_cast<__half2*>(&raw.y));
        acc[2] += f.x * di2; acc[3] += f.y * di2;
        f = __half22float2(*reinterpret_cast<__half2*>(&raw.z));
        acc[4] += f.x * di2; acc[5] += f.y * di2;
        f = __half22float2(*reinterpret_cast<__half2*>(&raw.w));
        acc[6] += f.x * di2; acc[7] += f.y * di2;
    } else {
        #pragma unroll
        for (int i = 0; i < 8; i++) acc[i] = 0.f;
    }

    for (int j0 = 0; j0 < cnt; j0 += 32) {
        int e = base + j0 + lane;
        bool ok = (j0 + lane) < cnt;
        int   s_l = ok ? esrc[e] : 0;
        float w_l = ok ? dinv[s_l] * di : 0.f;
        int m = min(32, cnt - j0);
        int iters = (m + 1) >> 1;
        #pragma unroll 4
        for (int k = 0; k < iters; k++) {
            int idx = 2 * k + g;
            int   ss = __shfl_sync(0xffffffffu, s_l, idx);
            float ww = __shfl_sync(0xffffffffu, w_l, idx);
            uint4 raw = reinterpret_cast<const uint4*>(h + (size_t)ss * HID)[sl];
            float2 f;
            f = __half22float2(*reinterpret_cast<__half2*>(&raw.x));
            acc[0] += f.x * ww; acc[1] += f.y * ww;
            f = __half22float2(*reinterpret_cast<__half2*>(&raw.y));
            acc[2] += f.x * ww; acc[3] += f.y * ww;
            f = __half22float2(*reinterpret_cast<__half2*>(&raw.z));
            acc[4] += f.x * ww; acc[5] += f.y * ww;
            f = __half22float2(*reinterpret_cast<__half2*>(&raw.w));
            acc[6] += f.x * ww; acc[7] += f.y * ww;
        }
    }

    #pragma unroll
    for (int i = 0; i < 8; i++)
        acc[i] += __shfl_down_sync(0xffffffffu, acc[i], 16);
    if (g == 0) {
        uint4 outp;
        *reinterpret_cast<__half2*>(&outp.x) = __floats2half2_rn(acc[0], acc[1]);
        *reinterpret_cast<__half2*>(&outp.y) = __floats2half2_rn(acc[2], acc[3]);
        *reinterpret_cast<__half2*>(&outp.z) = __floats2half2_rn(acc[4], acc[5]);
        *reinterpret_cast<__half2*>(&outp.w) = __floats2half2_rn(acc[6], acc[7]);
        reinterpret_cast<uint4*>(o + (size_t)warp * HID)[sl] = outp;
    }
}

// ---------------- pipelined tf32 tensor-core GEMM ----------------------------
// A and/or B may be fp16 (A_HALF/B_HALF): converted exactly to fp32 at
// fragment load, fed to tf32 MMA.
__device__ __forceinline__ void mma_tf32(float c[4], uint32_t a0, uint32_t a1,
                                         uint32_t a2, uint32_t a3,
                                         uint32_t b0, uint32_t b1) {
    asm volatile(
        "mma.sync.aligned.m16n8k8.row.col.f32.tf32.tf32.f32 "
        "{%0,%1,%2,%3}, {%4,%5,%6,%7}, {%8,%9}, {%0,%1,%2,%3};"
        : "+f"(c[0]), "+f"(c[1]), "+f"(c[2]), "+f"(c[3])
        : "r"(a0), "r"(a1), "r"(a2), "r"(a3), "r"(b0), "r"(b1));
}
__device__ __forceinline__ void cpasync16(uint32_t dst, const void* src, int sz) {
    asm volatile("cp.async.cg.shared.global [%0], [%1], 16, %2;"
                 :: "r"(dst), "l"(src), "r"(sz));
}
__device__ __forceinline__ void cp_commit() { asm volatile("cp.async.commit_group;"); }
__device__ __forceinline__ void cp_wait0()  { asm volatile("cp.async.wait_group 0;"); }

#define APAD_F 36
#define APAD_H 40
#define A_BYTES(AH) ((AH) ? (2 * 128 * APAD_H * 2) : (2 * 128 * APAD_F * 4))
#define BPAD(BN) ((BN) + 8)
#define B_BYTES(BH, BN) ((BH) ? (2 * 32 * BPAD(BN) * 2) : (2 * 32 * BPAD(BN) * 4))
#define GEMM_SMEM(AH, BH, BN) (A_BYTES(AH) + B_BYTES(BH, BN))

template<bool RELU_A, bool BIAS, bool OUT_HALF, bool A_HALF, bool B_HALF, int BN>
__global__ __launch_bounds__(256)
void tf32gemm(const void* __restrict__ Av,
              const void* __restrict__ Bv,
              void* __restrict__ Cv,
              const float* __restrict__ bias,
              int M, int N, int K, int ldb) {
    const int BM = 128, BK = 32;
    const int NT = BN / 16;
    extern __shared__ __align__(16) uint32_t smem[];
    uint32_t (*Asf)[BM][APAD_F] = reinterpret_cast<uint32_t (*)[BM][APAD_F]>(smem);
    __half   (*Ash)[BM][APAD_H] = reinterpret_cast<__half (*)[BM][APAD_H]>(smem);
    uint32_t* bbase = smem + A_BYTES(A_HALF) / 4;
    uint32_t (*Bsf)[BK][BPAD(BN)] =
        reinterpret_cast<uint32_t (*)[BK][BPAD(BN)]>(bbase);
    __half   (*Bsh)[BK][BPAD(BN)] =
        reinterpret_cast<__half (*)[BK][BPAD(BN)]>(bbase);

    int tid  = threadIdx.x;
    int lane = tid & 31;
    int wid  = tid >> 5;
    int gid  = lane >> 2;
    int tig  = lane & 3;
    int wm   = (wid & 3) * 32;
    int wn   = (wid >> 2) * (BN / 2);

    int row0 = blockIdx.y * BM;
    int col0 = blockIdx.x * BN;

    uint32_t sA = (uint32_t)__cvta_generic_to_shared(&smem[0]);
    uint32_t sB = (uint32_t)__cvta_generic_to_shared(bbase);

    float acc[2][NT][4];
    #pragma unroll
    for (int mt = 0; mt < 2; mt++)
        #pragma unroll
        for (int nt = 0; nt < NT; nt++)
            #pragma unroll
            for (int r = 0; r < 4; r++) acc[mt][nt][r] = 0.f;

    auto loadA = [&](int k0, int st) {
        if (A_HALF) {
            const __half* A = (const __half*)Av;
            int aRow = tid >> 2;
            int aC8  = (tid & 3) * 8;
            #pragma unroll
            for (int i = 0; i < 2; i++) {
                int row = aRow + i * 64;
                int gr  = row0 + row;
                int grc = gr < M ? gr : M - 1;
                const __half* src = A + (size_t)grc * K + k0 + aC8;
                uint32_t dst = sA + ((st * BM + row) * APAD_H + aC8) * 2;
                cpasync16(dst, src, gr < M ? 16 : 0);
            }
        } else {
            const float* A = (const float*)Av;
            int aRow = tid >> 3;
            int aC4  = (tid & 7) * 4;
            #pragma unroll
            for (int i = 0; i < 4; i++) {
                int row = aRow + i * 32;
                int gr  = row0 + row;
                int grc = gr < M ? gr : M - 1;
                const float* src = A + (size_t)grc * K + k0 + aC4;
                uint32_t dst = sA + ((st * BM + row) * APAD_F + aC4) * 4;
                cpasync16(dst, src, gr < M ? 16 : 0);
            }
        }
    };
    auto loadB = [&](int k0, int st) {
        if (B_HALF) {
            const __half* B = (const __half*)Bv;
            int bRow = tid / (BN / 8);          // 8 halves per 16B chunk
            int bC8  = (tid % (BN / 8)) * 8;
            const int STEP = 256 / (BN / 8);
            #pragma unroll
            for (int i = 0; i < 32 / STEP; i++) {
                int row = bRow + i * STEP;
                int gk  = k0 + row;
                int gc  = col0 + bC8;
                int rem = N - gc;
                int sz  = rem >= 8 ? 16 : (rem > 0 ? rem * 2 : 0);
                const __half* src = B + (size_t)gk * ldb + (rem > 0 ? gc : 0);
                uint32_t dst = sB + ((st * BK + row) * BPAD(BN) + bC8) * 2;
                cpasync16(dst, src, sz);
            }
        } else {
            const float* B = (const float*)Bv;
            int bRow = tid / (BN / 4);
            int bC4  = (tid % (BN / 4)) * 4;
            const int STEP = 256 / (BN / 4);
            #pragma unroll
            for (int i = 0; i < 32 / STEP; i++) {
                int row = bRow + i * STEP;
                int gk  = k0 + row;
                int gc  = col0 + bC4;
                int rem = N - gc;
                int sz  = rem >= 4 ? 16 : (rem > 0 ? rem * 4 : 0);
                const float* src = B + (size_t)gk * ldb + (rem > 0 ? gc : 0);
                uint32_t dst = sB + ((st * BK + row) * BPAD(BN) + bC4) * 4;
                cpasync16(dst, src, sz);
            }
        }
    };

    auto fragA = [&](int st, int r, int k) -> uint32_t {
        float v;
        if (A_HALF) v = __half2float(Ash[st][r][k]);
        else        v = __uint_as_float(Asf[st][r][k]);
        if (RELU_A) v = fmaxf(v, 0.f);
        return __float_as_uint(v);
    };
    auto fragB = [&](int st, int k, int c) -> uint32_t {
        if (B_HALF) return __float_as_uint(__half2float(Bsh[st][k][c]));
        else        return Bsf[st][k][c];
    };

    int KT = K / BK;
    loadA(0, 0); loadB(0, 0);
    cp_commit();

    for (int kt = 0; kt < KT; kt++) {
        cp_wait0();
        __syncthreads();
        if (kt + 1 < KT) {
            loadA((kt + 1) * BK, (kt + 1) & 1);
            loadB((kt + 1) * BK, (kt + 1) & 1);
            cp_commit();
        }
        int st = kt & 1;
        #pragma unroll
        for (int kc = 0; kc < 4; kc++) {
            int ks = kc * 8;
            uint32_t a[2][4];
            #pragma unroll
            for (int mt = 0; mt < 2; mt++) {
                int r = wm + mt * 16 + gid;
                a[mt][0] = fragA(st, r,     ks + tig);
                a[mt][1] = fragA(st, r + 8, ks + tig);
                a[mt][2] = fragA(st, r,     ks + tig + 4);
                a[mt][3] = fragA(st, r + 8, ks + tig + 4);
            }
            uint32_t b[NT][2];
            #pragma unroll
            for (int nt = 0; nt < NT; nt++) {
                int c = wn + nt * 8 + gid;
                b[nt][0] = fragB(st, ks + tig,     c);
                b[nt][1] = fragB(st, ks + tig + 4, c);
            }
            #pragma unroll
            for (int mt = 0; mt < 2; mt++)
                #pragma unroll
                for (int nt = 0; nt < NT; nt++)
                    mma_tf32(acc[mt][nt], a[mt][0], a[mt][1], a[mt][2], a[mt][3],
                             b[nt][0], b[nt][1]);
        }
        __syncthreads();
    }

    #pragma unroll
    for (int mt = 0; mt < 2; mt++) {
        #pragma unroll
        for (int rr = 0; rr < 2; rr++) {
            int gr = row0 + wm + mt * 16 + gid + rr * 8;
            if (gr >= M) continue;
            #pragma unroll
            for (int nt = 0; nt < NT; nt++) {
                int gc = col0 + wn + nt * 8 + tig * 2;
                float v0 = acc[mt][nt][rr * 2 + 0];
                float v1 = acc[mt][nt][rr * 2 + 1];
                if (OUT_HALF) {
                    __half* Ch = (__half*)Cv;
                    *reinterpret_cast<__half2*>(Ch + (size_t)gr * N + gc) =
                        __floats2half2_rn(v0, v1);
                } else {
                    float* Cf = (float*)Cv;
                    if (gc + 1 < N) {
                        float* cp = Cf + (size_t)gr * N + gc;
                        if (BIAS) {
                            *reinterpret_cast<float2*>(cp) =
                                make_float2(v0 + bias[gc], v1 + bias[gc + 1]);
                        } else {
                            *reinterpret_cast<float2*>(cp) = make_float2(v0, v1);
                        }
                    } else if (gc < N) {
                        Cf[(size_t)gr * N + gc] = BIAS ? v0 + bias[gc] : v0;
                    }
                }
            }
        }
    }
}

// ---------------- launch ------------------------------------------------------
extern "C" void kernel_launch(void* const* d_in, const int* in_sizes, int n_in,
                              void* d_out, int out_size) {
    const float* x    = (const float*)d_in[0];
    const int*   ei   = (const int*)d_in[1];
    const float* text = (const float*)d_in[2];
    const float* W1   = (const float*)d_in[3];
    const float* b1   = (const float*)d_in[4];
    const float* W2   = (const float*)d_in[5];
    const float* b2   = (const float*)d_in[6];
    const float* Wc   = (const float*)d_in[7];
    const float* bc   = (const float*)d_in[8];
    float* out = (float*)d_out;

    float *deg, *tv;
    __half *h1, *o1, *h2, *o2, *W2h, *Wch;
    int *ecnt, *offs, *cursor, *esrc, *counter;
    cudaGetSymbolAddress((void**)&deg,    g_deg);
    cudaGetSymbolAddress((void**)&h1,     g_h1);
    cudaGetSymbolAddress((void**)&o1,     g_o1);
    cudaGetSymbolAddress((void**)&h2,     g_h2);
    cudaGetSymbolAddress((void**)&o2,     g_o2);
    cudaGetSymbolAddress((void**)&tv,     g_tvec);
    cudaGetSymbolAddress((void**)&W2h,    g_W2h);
    cudaGetSymbolAddress((void**)&Wch,    g_Wch);
    cudaGetSymbolAddress((void**)&ecnt,   g_ecnt);
    cudaGetSymbolAddress((void**)&offs,   g_offs);
    cudaGetSymbolAddress((void**)&cursor, g_cursor);
    cudaGetSymbolAddress((void**)&esrc,   g_esrc);
    cudaGetSymbolAddress((void**)&counter,g_counter);

    cudaFuncSetAttribute(tf32gemm<false, false, true, false, false, 64>,
                         cudaFuncAttributeMaxDynamicSharedMemorySize,
                         GEMM_SMEM(false, false, 64));
    cudaFuncSetAttribute(tf32gemm<true, false, true, true, true, 64>,
                         cudaFuncAttributeMaxDynamicSharedMemorySize,
                         GEMM_SMEM(true, true, 64));
    cudaFuncSetAttribute(tf32gemm<false, true, false, true, true, 128>,
                         cudaFuncAttributeMaxDynamicSharedMemorySize,
                         GEMM_SMEM(true, true, 128));

    const int* srcp = ei;
    const int* dstp = ei + NE;

    cudaStream_t s2;
    cudaStreamCreateWithFlags(&s2, cudaStreamNonBlocking);
    cudaEvent_t eFork, eCSR, eWt, eTxt;
    cudaEventCreateWithFlags(&eFork, cudaEventDisableTiming);
    cudaEventCreateWithFlags(&eCSR,  cudaEventDisableTiming);
    cudaEventCreateWithFlags(&eWt,   cudaEventDisableTiming);
    cudaEventCreateWithFlags(&eTxt,  cudaEventDisableTiming);

    cudaEventRecord(eFork, 0);
    cudaStreamWaitEvent(s2, eFork, 0);

    // s2: prep chain + weight conversion + text projection (hidden under GEMM1)
    init_all   <<<(NN + 255) / 256, 256, 0, s2>>>(deg, tv, bc, counter);
    deg_count  <<<(NE + 255) / 256, 256, 0, s2>>>(dstp, deg);
    rsqrt_alloc<<<(NN + 255) / 256, 256, 0, s2>>>(deg, ecnt, offs, cursor, counter);
    fill_edges <<<(NE + 255) / 256, 256, 0, s2>>>(srcp, dstp, cursor, esrc);
    cudaEventRecord(eCSR, s2);
    convert_half<<<(HID * HID + 255) / 256, 256, 0, s2>>>(W2, W2h, HID * HID);
    convert_half<<<(HID * OUTC + 255) / 256, 256, 0, s2>>>(Wc, Wch, HID * OUTC);
    cudaEventRecord(eWt, s2);
    dim3 gtp((OUTC + 127) / 128, TDIM / 128);
    text_proj_part<<<gtp, 128, 0, s2>>>(text, Wc, tv);
    cudaEventRecord(eTxt, s2);

    dim3 gHid(2, (NN + 127) / 128);
    dim3 gOut((OUTC + 127) / 128, (NN + 127) / 128);
    int gatherBlocks = (NN * 32 + 255) / 256;

    // s0: GEMM1 (A fp32 x, B fp32 W1 -> h1 fp16)
    tf32gemm<false, false, true, false, false, 64>
        <<<gHid, 256, GEMM_SMEM(false, false, 64)>>>(
        x, W1, h1, nullptr, NN, HID, INC, HID);

    // join CSR; gather1
    cudaStreamWaitEvent(0, eCSR, 0);
    gather_edges<<<gatherBlocks, 256>>>(offs, ecnt, esrc, h1, deg, b1, o1);

    // layer 2 (A fp16 o1 + relu, B fp16 W2h -> h2 fp16)
    cudaStreamWaitEvent(0, eWt, 0);
    tf32gemm<true, false, true, true, true, 64>
        <<<gHid, 256, GEMM_SMEM(true, true, 64)>>>(
        o1, W2h, h2, nullptr, NN, HID, HID, HID);
    gather_edges<<<gatherBlocks, 256>>>(offs, ecnt, esrc, h2, deg, b2, o2);

    // classifier (A fp16 o2, B fp16 Wch -> out fp32 + tvec)
    cudaStreamWaitEvent(0, eTxt, 0);
    tf32gemm<false, true, false, true, true, 128>
        <<<gOut, 256, GEMM_SMEM(true, true, 128)>>>(
        o2, Wch, out, tv, NN, OUTC, HID, OUTC);
}

// round 16
// speedup vs baseline: 1.0258x; 1.0258x over previous
#include <cuda_runtime.h>
#include <cuda_fp16.h>
#include <cstdint>

#define NN 50000
#define NE 800000
#define INC 256
#define HID 128
#define OUTC 1000
#define TDIM 768

// ---------------- scratch ----------------------------------------------------
__device__ __align__(256) float  g_deg[NN];
__device__ __align__(256) __half g_h1[(size_t)NN * HID];
__device__ __align__(256) __half g_o1[(size_t)NN * HID];
__device__ __align__(256) __half g_h2[(size_t)NN * HID];
__device__ __align__(256) __half g_o2[(size_t)NN * HID];
__device__ __align__(256) float  g_tvec[1024];
__device__ __align__(256) int    g_ecnt[NN];
__device__ __align__(256) int    g_offs[NN];
__device__ __align__(256) int    g_cursor[NN];
__device__ __align__(256) int    g_esrc[NE];
__device__ int g_counter;

// ---------------- prep kernels ------------------------------------------------
__global__ void init_all(float* deg, float* tvec, const float* __restrict__ bc,
                         int* counter) {
    int i = blockIdx.x * blockDim.x + threadIdx.x;
    if (i == 0) *counter = 0;
    if (i < NN) deg[i] = 1.0f;
    if (i < OUTC) tvec[i] = bc[i];
}
__global__ void deg_count(const int* __restrict__ dst, float* deg) {
    int e = blockIdx.x * blockDim.x + threadIdx.x;
    if (e < NE) atomicAdd(&deg[dst[e]], 1.0f);
}
__global__ void rsqrt_alloc(float* deg, int* ecnt, int* offs, int* cursor,
                            int* counter) {
    int i = blockIdx.x * blockDim.x + threadIdx.x;
    if (i >= NN) return;
    float d = deg[i];
    int c = (int)d - 1;
    ecnt[i] = c;
    deg[i] = rsqrtf(d);
    int base = atomicAdd(counter, c);
    offs[i] = base;
    cursor[i] = base;
}
__global__ void fill_edges(const int* __restrict__ src,
                           const int* __restrict__ dst,
                           int* __restrict__ cursor,
                           int* __restrict__ esrc) {
    int e = blockIdx.x * blockDim.x + threadIdx.x;
    if (e >= NE) return;
    int pos = atomicAdd(&cursor[dst[e]], 1);
    esrc[pos] = src[e];
}
__global__ void text_proj_part(const float* __restrict__ text,
                               const float* __restrict__ Wc,
                               float* __restrict__ tvec) {
    int o = blockIdx.x * 128 + threadIdx.x;
    int d0 = blockIdx.y * 128;
    if (o >= OUTC) return;
    float s = 0.f;
    #pragma unroll 8
    for (int d = d0; d < d0 + 128; d++)
        s += text[d] * Wc[(size_t)(HID + d) * OUTC + o];
    atomicAdd(&tvec[o], s);
}

// ---------------- CSR gather (h fp16 in, o fp16 out, fp32 accumulation) ------
__global__ void gather_edges(const int* __restrict__ offs,
                             const int* __restrict__ ecnt,
                             const int* __restrict__ esrc,
                             const __half* __restrict__ h,
                             const float* __restrict__ dinv,
                             const float* __restrict__ bias,
                             __half* __restrict__ o) {
    int warp = (blockIdx.x * blockDim.x + threadIdx.x) >> 5;
    int lane = threadIdx.x & 31;
    if (warp >= NN) return;
    int base = offs[warp];
    int end  = base + ecnt[warp];
    float di = dinv[warp];
    float di2 = di * di;
    float4 acc = reinterpret_cast<const float4*>(bias)[lane];
    {   // self contribution
        uint2 raw = reinterpret_cast<const uint2*>(h + (size_t)warp * HID)[lane];
        float2 f0 = __half22float2(*reinterpret_cast<__half2*>(&raw.x));
        float2 f1 = __half22float2(*reinterpret_cast<__half2*>(&raw.y));
        acc.x += f0.x * di2; acc.y += f0.y * di2;
        acc.z += f1.x * di2; acc.w += f1.y * di2;
    }
    for (int j0 = base; j0 < end; j0 += 32) {
        int e = j0 + lane;
        bool ok = e < end;
        int   s_l = ok ? esrc[e] : 0;
        float w_l = ok ? dinv[s_l] * di : 0.f;
        int m = min(32, end - j0);
        #pragma unroll 8
        for (int k = 0; k < m; k++) {
            int   ss = __shfl_sync(0xffffffffu, s_l, k);
            float ww = __shfl_sync(0xffffffffu, w_l, k);
            uint2 raw = reinterpret_cast<const uint2*>(h + (size_t)ss * HID)[lane];
            float2 f0 = __half22float2(*reinterpret_cast<__half2*>(&raw.x));
            float2 f1 = __half22float2(*reinterpret_cast<__half2*>(&raw.y));
            acc.x += f0.x * ww; acc.y += f0.y * ww;
            acc.z += f1.x * ww; acc.w += f1.y * ww;
        }
    }
    uint2 outp;
    *reinterpret_cast<__half2*>(&outp.x) = __floats2half2_rn(acc.x, acc.y);
    *reinterpret_cast<__half2*>(&outp.y) = __floats2half2_rn(acc.z, acc.w);
    reinterpret_cast<uint2*>(o + (size_t)warp * HID)[lane] = outp;
}

// ---------------- pipelined tf32 tensor-core GEMM ----------------------------
// A may be fp32 or fp16 (A_HALF); converted exactly to fp32 at fragment load,
// fed to tf32 MMA. B always fp32. Output fp32 (+bias) or fp16.
__device__ __forceinline__ void mma_tf32(float c[4], uint32_t a0, uint32_t a1,
                                         uint32_t a2, uint32_t a3,
                                         uint32_t b0, uint32_t b1) {
    asm volatile(
        "mma.sync.aligned.m16n8k8.row.col.f32.tf32.tf32.f32 "
        "{%0,%1,%2,%3}, {%4,%5,%6,%7}, {%8,%9}, {%0,%1,%2,%3};"
        : "+f"(c[0]), "+f"(c[1]), "+f"(c[2]), "+f"(c[3])
        : "r"(a0), "r"(a1), "r"(a2), "r"(a3), "r"(b0), "r"(b1));
}
__device__ __forceinline__ void cpasync16(uint32_t dst, const void* src, int sz) {
    asm volatile("cp.async.cg.shared.global [%0], [%1], 16, %2;"
                 :: "r"(dst), "l"(src), "r"(sz));
}
__device__ __forceinline__ void cp_commit() { asm volatile("cp.async.commit_group;"); }
__device__ __forceinline__ void cp_wait0()  { asm volatile("cp.async.wait_group 0;"); }

#define APAD_F 36
#define APAD_H 40
#define A_BYTES(AH) ((AH) ? (2 * 128 * APAD_H * 2) : (2 * 128 * APAD_F * 4))
#define BPAD(BN) ((BN) + 8)
#define B_BYTES(BN) (2 * 32 * BPAD(BN) * 4)
#define GEMM_SMEM(AH, BN) (A_BYTES(AH) + B_BYTES(BN))

template<bool RELU_A, bool BIAS, bool OUT_HALF, bool A_HALF, int BN>
__global__ __launch_bounds__(256)
void tf32gemm(const void* __restrict__ Av,
              const float* __restrict__ B,
              void* __restrict__ Cv,
              const float* __restrict__ bias,
              int M, int N, int K, int ldb) {
    const int BM = 128, BK = 32;
    const int NT = BN / 16;
    extern __shared__ __align__(16) uint32_t smem[];
    uint32_t (*Asf)[BM][APAD_F] = reinterpret_cast<uint32_t (*)[BM][APAD_F]>(smem);
    __half   (*Ash)[BM][APAD_H] = reinterpret_cast<__half (*)[BM][APAD_H]>(smem);
    uint32_t (*Bs)[BK][BPAD(BN)] =
        reinterpret_cast<uint32_t (*)[BK][BPAD(BN)]>(smem + A_BYTES(A_HALF) / 4);

    int tid  = threadIdx.x;
    int lane = tid & 31;
    int wid  = tid >> 5;
    int gid  = lane >> 2;
    int tig  = lane & 3;
    int wm   = (wid & 3) * 32;
    int wn   = (wid >> 2) * (BN / 2);

    int row0 = blockIdx.y * BM;
    int col0 = blockIdx.x * BN;

    uint32_t sA = (uint32_t)__cvta_generic_to_shared(&smem[0]);
    uint32_t sB = (uint32_t)__cvta_generic_to_shared(&Bs[0][0][0]);

    float acc[2][NT][4];
    #pragma unroll
    for (int mt = 0; mt < 2; mt++)
        #pragma unroll
        for (int nt = 0; nt < NT; nt++)
            #pragma unroll
            for (int r = 0; r < 4; r++) acc[mt][nt][r] = 0.f;

    int bRow = tid / (BN / 4);
    int bC4  = (tid % (BN / 4)) * 4;
    const int BROWSTEP = 256 / (BN / 4);

    auto loadA = [&](int k0, int st) {
        if (A_HALF) {
            const __half* A = (const __half*)Av;
            int aRow = tid >> 2;
            int aC8  = (tid & 3) * 8;
            #pragma unroll
            for (int i = 0; i < 2; i++) {
                int row = aRow + i * 64;
                int gr  = row0 + row;
                int grc = gr < M ? gr : M - 1;
                const __half* src = A + (size_t)grc * K + k0 + aC8;
                uint32_t dst = sA + ((st * BM + row) * APAD_H + aC8) * 2;
                cpasync16(dst, src, gr < M ? 16 : 0);
            }
        } else {
            const float* A = (const float*)Av;
            int aRow = tid >> 3;
            int aC4  = (tid & 7) * 4;
            #pragma unroll
            for (int i = 0; i < 4; i++) {
                int row = aRow + i * 32;
                int gr  = row0 + row;
                int grc = gr < M ? gr : M - 1;
                const float* src = A + (size_t)grc * K + k0 + aC4;
                uint32_t dst = sA + ((st * BM + row) * APAD_F + aC4) * 4;
                cpasync16(dst, src, gr < M ? 16 : 0);
            }
        }
    };
    auto loadB = [&](int k0, int st) {
        #pragma unroll
        for (int i = 0; i < 32 / BROWSTEP; i++) {
            int row = bRow + i * BROWSTEP;
            int gk  = k0 + row;
            int gc  = col0 + bC4;
            int rem = N - gc;
            int sz  = rem >= 4 ? 16 : (rem > 0 ? rem * 4 : 0);
            const float* src = B + (size_t)gk * ldb + (rem > 0 ? gc : 0);
            uint32_t dst = sB + (((st * BK + row) * BPAD(BN)) + bC4) * 4;
            cpasync16(dst, src, sz);
        }
    };

    auto fragA = [&](int st, int r, int k) -> uint32_t {
        float v;
        if (A_HALF) v = __half2float(Ash[st][r][k]);
        else        v = __uint_as_float(Asf[st][r][k]);
        if (RELU_A) v = fmaxf(v, 0.f);
        return __float_as_uint(v);
    };

    int KT = K / BK;
    loadA(0, 0); loadB(0, 0);
    cp_commit();

    for (int kt = 0; kt < KT; kt++) {
        cp_wait0();
        __syncthreads();
        if (kt + 1 < KT) {
            loadA((kt + 1) * BK, (kt + 1) & 1);
            loadB((kt + 1) * BK, (kt + 1) & 1);
            cp_commit();
        }
        int st = kt & 1;
        #pragma unroll
        for (int kc = 0; kc < 4; kc++) {
            int ks = kc * 8;
            uint32_t a[2][4];
            #pragma unroll
            for (int mt = 0; mt < 2; mt++) {
                int r = wm + mt * 16 + gid;
                a[mt][0] = fragA(st, r,     ks + tig);
                a[mt][1] = fragA(st, r + 8, ks + tig);
                a[mt][2] = fragA(st, r,     ks + tig + 4);
                a[mt][3] = fragA(st, r + 8, ks + tig + 4);
            }
            uint32_t b[NT][2];
            #pragma unroll
            for (int nt = 0; nt < NT; nt++) {
                int c = wn + nt * 8 + gid;
                b[nt][0] = Bs[st][ks + tig    ][c];
                b[nt][1] = Bs[st][ks + tig + 4][c];
            }
            #pragma unroll
            for (int mt = 0; mt < 2; mt++)
                #pragma unroll
                for (int nt = 0; nt < NT; nt++)
                    mma_tf32(acc[mt][nt], a[mt][0], a[mt][1], a[mt][2], a[mt][3],
                             b[nt][0], b[nt][1]);
        }
        __syncthreads();
    }

    #pragma unroll
    for (int mt = 0; mt < 2; mt++) {
        #pragma unroll
        for (int rr = 0; rr < 2; rr++) {
            int gr = row0 + wm + mt * 16 + gid + rr * 8;
            if (gr >= M) continue;
            #pragma unroll
            for (int nt = 0; nt < NT; nt++) {
                int gc = col0 + wn + nt * 8 + tig * 2;
                float v0 = acc[mt][nt][rr * 2 + 0];
                float v1 = acc[mt][nt][rr * 2 + 1];
                if (OUT_HALF) {
                    __half* Ch = (__half*)Cv;
                    *reinterpret_cast<__half2*>(Ch + (size_t)gr * N + gc) =
                        __floats2half2_rn(v0, v1);
                } else {
                    float* Cf = (float*)Cv;
                    if (gc + 1 < N) {
                        float* cp = Cf + (size_t)gr * N + gc;
                        if (BIAS) {
                            *reinterpret_cast<float2*>(cp) =
                                make_float2(v0 + bias[gc], v1 + bias[gc + 1]);
                        } else {
                            *reinterpret_cast<float2*>(cp) = make_float2(v0, v1);
                        }
                    } else if (gc < N) {
                        Cf[(size_t)gr * N + gc] = BIAS ? v0 + bias[gc] : v0;
                    }
                }
            }
        }
    }
}

// ---------------- launch ------------------------------------------------------
extern "C" void kernel_launch(void* const* d_in, const int* in_sizes, int n_in,
                              void* d_out, int out_size) {
    const float* x    = (const float*)d_in[0];
    const int*   ei   = (const int*)d_in[1];
    const float* text = (const float*)d_in[2];
    const float* W1   = (const float*)d_in[3];
    const float* b1   = (const float*)d_in[4];
    const float* W2   = (const float*)d_in[5];
    const float* b2   = (const float*)d_in[6];
    const float* Wc   = (const float*)d_in[7];
    const float* bc   = (const float*)d_in[8];
    float* out = (float*)d_out;

    float *deg, *tv;
    __half *h1, *o1, *h2, *o2;
    int *ecnt, *offs, *cursor, *esrc, *counter;
    cudaGetSymbolAddress((void**)&deg,    g_deg);
    cudaGetSymbolAddress((void**)&h1,     g_h1);
    cudaGetSymbolAddress((void**)&o1,     g_o1);
    cudaGetSymbolAddress((void**)&h2,     g_h2);
    cudaGetSymbolAddress((void**)&o2,     g_o2);
    cudaGetSymbolAddress((void**)&tv,     g_tvec);
    cudaGetSymbolAddress((void**)&ecnt,   g_ecnt);
    cudaGetSymbolAddress((void**)&offs,   g_offs);
    cudaGetSymbolAddress((void**)&cursor, g_cursor);
    cudaGetSymbolAddress((void**)&esrc,   g_esrc);
    cudaGetSymbolAddress((void**)&counter,g_counter);

    cudaFuncSetAttribute(tf32gemm<false, false, true, false, 64>,
                         cudaFuncAttributeMaxDynamicSharedMemorySize,
                         GEMM_SMEM(false, 64));
    cudaFuncSetAttribute(tf32gemm<true, false, true, true, 64>,
                         cudaFuncAttributeMaxDynamicSharedMemorySize,
                         GEMM_SMEM(true, 64));
    cudaFuncSetAttribute(tf32gemm<false, true, false, true, 128>,
                         cudaFuncAttributeMaxDynamicSharedMemorySize,
                         GEMM_SMEM(true, 128));

    const int* srcp = ei;
    const int* dstp = ei + NE;

    cudaStream_t s2;
    cudaStreamCreateWithFlags(&s2, cudaStreamNonBlocking);
    cudaEvent_t eFork, eCSR, eTxt;
    cudaEventCreateWithFlags(&eFork, cudaEventDisableTiming);
    cudaEventCreateWithFlags(&eCSR,  cudaEventDisableTiming);
    cudaEventCreateWithFlags(&eTxt,  cudaEventDisableTiming);

    cudaEventRecord(eFork, 0);
    cudaStreamWaitEvent(s2, eFork, 0);

    // s2: prep chain + text projection (hidden under GEMM1)
    init_all   <<<(NN + 255) / 256, 256, 0, s2>>>(deg, tv, bc, counter);
    deg_count  <<<(NE + 255) / 256, 256, 0, s2>>>(dstp, deg);
    rsqrt_alloc<<<(NN + 255) / 256, 256, 0, s2>>>(deg, ecnt, offs, cursor, counter);
    fill_edges <<<(NE + 255) / 256, 256, 0, s2>>>(srcp, dstp, cursor, esrc);
    cudaEventRecord(eCSR, s2);
    dim3 gtp((OUTC + 127) / 128, TDIM / 128);
    text_proj_part<<<gtp, 128, 0, s2>>>(text, Wc, tv);
    cudaEventRecord(eTxt, s2);

    dim3 gHid(2, (NN + 127) / 128);
    dim3 gOut((OUTC + 127) / 128, (NN + 127) / 128);
    int gatherBlocks = (NN * 32 + 255) / 256;

    // s0: GEMM1 (A fp32 x, B fp32 W1 -> h1 fp16)
    tf32gemm<false, false, true, false, 64><<<gHid, 256, GEMM_SMEM(false, 64)>>>(
        x, W1, h1, nullptr, NN, HID, INC, HID);

    // join CSR; gather1 (bias+self fused)
    cudaStreamWaitEvent(0, eCSR, 0);
    gather_edges<<<gatherBlocks, 256>>>(offs, ecnt, esrc, h1, deg, b1, o1);

    // layer 2 (A fp16 o1 + relu, B fp32 W2 -> h2 fp16)
    tf32gemm<true, false, true, true, 64><<<gHid, 256, GEMM_SMEM(true, 64)>>>(
        o1, W2, h2, nullptr, NN, HID, HID, HID);
    gather_edges<<<gatherBlocks, 256>>>(offs, ecnt, esrc, h2, deg, b2, o2);

    // classifier (A fp16 o2, B fp32 Wc -> out fp32 + tvec)
    cudaStreamWaitEvent(0, eTxt, 0);
    tf32gemm<false, true, false, true, 128><<<gOut, 256, GEMM_SMEM(true, 128)>>>(
        o2, Wc, out, tv, NN, OUTC, HID, OUTC);
}